// round 4
// baseline (speedup 1.0000x reference)
#include <cuda_runtime.h>
#include <math.h>
#include <float.h>

#define N_NODES 100000
#define N_EDGES 1600000
#define ETOT    (N_EDGES + N_NODES)
#define IN_DIM  256
#define HID     128
#define OUTD    64
#define NEG_SLOPE 0.2f
#define SCAN_NB ((N_NODES + 255) / 256)   // 391
#define FULLM 0xffffffffu

// ---------------- scratch (static device globals; no allocation) ----------------
static __device__ __align__(128) float g_h1[(size_t)N_NODES * HID];   // x@W1
static __device__ __align__(128) float g_o1[(size_t)N_NODES * HID];   // elu(agg1 + b1)
static __device__ __align__(128) float g_h2[(size_t)N_NODES * OUTD];  // o1@W2
static __device__ float g_ssrc[N_NODES];
static __device__ float g_sdst[N_NODES];
static __device__ int   g_cnt[N_NODES];
static __device__ int   g_cur[N_NODES];
static __device__ int   g_off[N_NODES + 1];
static __device__ int   g_bsum[512];
static __device__ int   g_col[ETOT];

// ---------------- CSR build ----------------
__global__ void k_zeroA() {
    int i = blockIdx.x * blockDim.x + threadIdx.x;
    if (i < N_NODES) g_cnt[i] = 0;
}
__global__ void k_zeroB() {
    int i = blockIdx.x * blockDim.x + threadIdx.x;
    if (i < N_NODES) g_cur[i] = 0;
}

__global__ void k_count(const int* __restrict__ ei) {
    int t = blockIdx.x * blockDim.x + threadIdx.x;
    if (t >= ETOT) return;
    int dst = (t < N_EDGES) ? ei[N_EDGES + t] : (t - N_EDGES);
    atomicAdd(&g_cnt[dst], 1);
}

__global__ void k_scan1() {
    __shared__ int s[256];
    int t = threadIdx.x, idx = blockIdx.x * 256 + t;
    int v = (idx < N_NODES) ? g_cnt[idx] : 0;
    s[t] = v; __syncthreads();
    #pragma unroll
    for (int o = 1; o < 256; o <<= 1) {
        int u = (t >= o) ? s[t - o] : 0;
        __syncthreads();
        s[t] += u;
        __syncthreads();
    }
    if (idx < N_NODES) g_off[idx] = s[t] - v;
    if (t == 255) g_bsum[blockIdx.x] = s[t];
}

__global__ void k_scan2(int nb) {
    __shared__ int s[512];
    int t = threadIdx.x;
    int v = (t < nb) ? g_bsum[t] : 0;
    s[t] = v; __syncthreads();
    #pragma unroll
    for (int o = 1; o < 512; o <<= 1) {
        int u = (t >= o) ? s[t - o] : 0;
        __syncthreads();
        s[t] += u;
        __syncthreads();
    }
    g_bsum[t] = s[t] - v;
}

__global__ void k_scan3() {
    int t = threadIdx.x, idx = blockIdx.x * 256 + t;
    if (idx < N_NODES) g_off[idx] += g_bsum[blockIdx.x];
    if (idx == 0) g_off[N_NODES] = ETOT;
}

// CSR column fill (structure only)
__global__ void k_fill(const int* __restrict__ ei) {
    int t = blockIdx.x * blockDim.x + threadIdx.x;
    if (t >= ETOT) return;
    int src, dst;
    if (t < N_EDGES) { src = ei[t]; dst = ei[N_EDGES + t]; }
    else             { src = dst = t - N_EDGES; }
    int pos = g_off[dst] + atomicAdd(&g_cur[dst], 1);
    g_col[pos] = src;
}

// ---------------- GEMM v3 + fused attention-score epilogue ----------------
template<int K, int NCOL, int BM>
__global__ void k_gemm(const float* __restrict__ A, const float* __restrict__ W,
                       float* __restrict__ C,
                       const float* __restrict__ asrc, const float* __restrict__ adst,
                       float* __restrict__ ssrc, float* __restrict__ sdst, int M) {
    constexpr int TN = 4, TM = 8, BK = 16;
    constexpr int TX = NCOL / TN;
    constexpr int ALD = BM + 4;
    constexpr int NC4 = NCOL / 4;
    __shared__ float As[BK][ALD];
    __shared__ float Ws[BK][NCOL];
    const int tid = threadIdx.x;
    const int tx = tid % TX;
    const int ty = tid / TX;
    const int m0 = blockIdx.x * BM;

    float acc[TM][TN];
    #pragma unroll
    for (int r = 0; r < TM; r++)
        #pragma unroll
        for (int n = 0; n < TN; n++) acc[r][n] = 0.f;

    for (int k0 = 0; k0 < K; k0 += BK) {
        #pragma unroll
        for (int i = tid; i < BM * 4; i += 256) {
            int row = i >> 2, kf = (i & 3) * 4;
            float4 v = make_float4(0.f, 0.f, 0.f, 0.f);
            int gr = m0 + row;
            if (gr < M) v = *(const float4*)(A + (size_t)gr * K + k0 + kf);
            As[kf + 0][row] = v.x;
            As[kf + 1][row] = v.y;
            As[kf + 2][row] = v.z;
            As[kf + 3][row] = v.w;
        }
        #pragma unroll
        for (int i = tid; i < BK * NC4; i += 256) {
            int wr = i / NC4, wc = (i % NC4) * 4;
            *(float4*)&Ws[wr][wc] = *(const float4*)(W + (size_t)(k0 + wr) * NCOL + wc);
        }
        __syncthreads();
        #pragma unroll
        for (int kk = 0; kk < BK; kk++) {
            float4 a0 = *(const float4*)&As[kk][ty * TM];
            float4 a1 = *(const float4*)&As[kk][ty * TM + 4];
            float4 wv = *(const float4*)&Ws[kk][tx * TN];
            float a_[TM] = {a0.x, a0.y, a0.z, a0.w, a1.x, a1.y, a1.z, a1.w};
            float w_[TN] = {wv.x, wv.y, wv.z, wv.w};
            #pragma unroll
            for (int r = 0; r < TM; r++)
                #pragma unroll
                for (int n = 0; n < TN; n++)
                    acc[r][n] = fmaf(a_[r], w_[n], acc[r][n]);
        }
        __syncthreads();
    }

    #pragma unroll
    for (int r = 0; r < TM; r++) {
        int row = m0 + ty * TM + r;
        if (row < M) {
            float4 v = make_float4(acc[r][0], acc[r][1], acc[r][2], acc[r][3]);
            *(float4*)(C + (size_t)row * NCOL + tx * TN) = v;
        }
    }

    float4 a1v = *(const float4*)(asrc + tx * TN);
    float4 a2v = *(const float4*)(adst + tx * TN);
    float p1[TM], p2[TM];
    #pragma unroll
    for (int r = 0; r < TM; r++) {
        p1[r] = acc[r][0] * a1v.x + acc[r][1] * a1v.y + acc[r][2] * a1v.z + acc[r][3] * a1v.w;
        p2[r] = acc[r][0] * a2v.x + acc[r][1] * a2v.y + acc[r][2] * a2v.z + acc[r][3] * a2v.w;
    }
    #pragma unroll
    for (int o = TX / 2; o; o >>= 1) {
        #pragma unroll
        for (int r = 0; r < TM; r++) {
            p1[r] += __shfl_xor_sync(FULLM, p1[r], o);
            p2[r] += __shfl_xor_sync(FULLM, p2[r], o);
        }
    }
    if (tx == 0) {
        #pragma unroll
        for (int r = 0; r < TM; r++) {
            int row = m0 + ty * TM + r;
            if (row < M) { ssrc[row] = p1[r]; sdst[row] = p2[r]; }
        }
    }
}

// ---------------- online-softmax warp-per-dst aggregation ----------------
template<int F, bool ELU>
__global__ void k_agg(const float* __restrict__ h,
                      const float* __restrict__ ssrc, const float* __restrict__ sdst,
                      const float* __restrict__ bias, float* __restrict__ out) {
    constexpr int VEC = F / 32;
    int node = (blockIdx.x * blockDim.x + threadIdx.x) >> 5;
    if (node >= N_NODES) return;
    int lane = threadIdx.x & 31;
    int beg = g_off[node], end = g_off[node + 1];
    float sd = sdst[node];

    float m = -FLT_MAX, s = 0.f;
    float acc[VEC];
    #pragma unroll
    for (int v = 0; v < VEC; v++) acc[v] = 0.f;

    for (int c0 = beg; c0 < end; c0 += 32) {
        int n = min(32, end - c0);
        float e = -FLT_MAX; int cs = 0;
        if (lane < n) {
            cs = g_col[c0 + lane];
            float t = ssrc[cs] + sd;
            e = (t > 0.f) ? t : NEG_SLOPE * t;
        }
        float cm = e;
        #pragma unroll
        for (int o = 16; o; o >>= 1) cm = fmaxf(cm, __shfl_xor_sync(FULLM, cm, o));
        float mn = fmaxf(m, cm);
        float scale = __expf(m - mn);
        s *= scale;
        #pragma unroll
        for (int v = 0; v < VEC; v++) acc[v] *= scale;

        float w = (lane < n) ? __expf(e - mn) : 0.f;
        float ws = w;
        #pragma unroll
        for (int o = 16; o; o >>= 1) ws += __shfl_xor_sync(FULLM, ws, o);
        s += ws;
        m = mn;

        int k = 0;
        for (; k + 4 <= n; k += 4) {
            float w0 = __shfl_sync(FULLM, w, k);
            float w1 = __shfl_sync(FULLM, w, k + 1);
            float w2 = __shfl_sync(FULLM, w, k + 2);
            float w3 = __shfl_sync(FULLM, w, k + 3);
            int s0 = __shfl_sync(FULLM, cs, k);
            int s1 = __shfl_sync(FULLM, cs, k + 1);
            int s2 = __shfl_sync(FULLM, cs, k + 2);
            int s3 = __shfl_sync(FULLM, cs, k + 3);
            const float* p0 = h + (size_t)s0 * F + lane * VEC;
            const float* p1 = h + (size_t)s1 * F + lane * VEC;
            const float* p2 = h + (size_t)s2 * F + lane * VEC;
            const float* p3 = h + (size_t)s3 * F + lane * VEC;
            if (VEC == 4) {
                float4 v0 = *(const float4*)p0;
                float4 v1 = *(const float4*)p1;
                float4 v2 = *(const float4*)p2;
                float4 v3 = *(const float4*)p3;
                acc[0] = fmaf(w0, v0.x, acc[0]); acc[1] = fmaf(w0, v0.y, acc[1]);
                acc[2] = fmaf(w0, v0.z, acc[2]); acc[3] = fmaf(w0, v0.w, acc[3]);
                acc[0] = fmaf(w1, v1.x, acc[0]); acc[1] = fmaf(w1, v1.y, acc[1]);
                acc[2] = fmaf(w1, v1.z, acc[2]); acc[3] = fmaf(w1, v1.w, acc[3]);
                acc[0] = fmaf(w2, v2.x, acc[0]); acc[1] = fmaf(w2, v2.y, acc[1]);
                acc[2] = fmaf(w2, v2.z, acc[2]); acc[3] = fmaf(w2, v2.w, acc[3]);
                acc[0] = fmaf(w3, v3.x, acc[0]); acc[1] = fmaf(w3, v3.y, acc[1]);
                acc[2] = fmaf(w3, v3.z, acc[2]); acc[3] = fmaf(w3, v3.w, acc[3]);
            } else {
                float2 v0 = *(const float2*)p0;
                float2 v1 = *(const float2*)p1;
                float2 v2 = *(const float2*)p2;
                float2 v3 = *(const float2*)p3;
                acc[0] = fmaf(w0, v0.x, acc[0]); acc[1] = fmaf(w0, v0.y, acc[1]);
                acc[0] = fmaf(w1, v1.x, acc[0]); acc[1] = fmaf(w1, v1.y, acc[1]);
                acc[0] = fmaf(w2, v2.x, acc[0]); acc[1] = fmaf(w2, v2.y, acc[1]);
                acc[0] = fmaf(w3, v3.x, acc[0]); acc[1] = fmaf(w3, v3.y, acc[1]);
            }
        }
        for (; k < n; k++) {
            float w0 = __shfl_sync(FULLM, w, k);
            int s0 = __shfl_sync(FULLM, cs, k);
            const float* p0 = h + (size_t)s0 * F + lane * VEC;
            if (VEC == 4) {
                float4 v0 = *(const float4*)p0;
                acc[0] = fmaf(w0, v0.x, acc[0]); acc[1] = fmaf(w0, v0.y, acc[1]);
                acc[2] = fmaf(w0, v0.z, acc[2]); acc[3] = fmaf(w0, v0.w, acc[3]);
            } else {
                float2 v0 = *(const float2*)p0;
                acc[0] = fmaf(w0, v0.x, acc[0]); acc[1] = fmaf(w0, v0.y, acc[1]);
            }
        }
    }

    float inv = 1.f / s;
    #pragma unroll
    for (int v = 0; v < VEC; v++) {
        float bv = bias[lane * VEC + v];
        float r = acc[v] * inv + bv;
        if (ELU) r = (r > 0.f) ? r : expm1f(r);
        acc[v] = r;
    }
    if (VEC == 4) {
        float4 o4 = make_float4(acc[0], acc[1], acc[2], acc[3]);
        *(float4*)(out + (size_t)node * F + lane * 4) = o4;
    } else {
        float2 o2 = make_float2(acc[0], acc[1]);
        *(float2*)(out + (size_t)node * F + lane * 2) = o2;
    }
}

// ---------------- launch ----------------
// MEASUREMENT ROUND: kernels byte-identical to R3. agg128 / gemm2 / agg64 are
// idempotent (read-only inputs, overwrite outputs bit-identically), so each is
// launched TWICE: dur_us_R4 - dur_us_R3 = cost(agg128 + gemm2 + agg64).
// ncu's fixed capture slot (launch index 3) is pointed at k_scan1 (largest
// never-measured non-idempotent kernel).
extern "C" void kernel_launch(void* const* d_in, const int* in_sizes, int n_in,
                              void* d_out, int out_size) {
    const float* x   = (const float*)d_in[0];
    const int*   ei  = (const int*)d_in[1];
    const float* W1  = (const float*)d_in[2];
    const float* a1s = (const float*)d_in[3];
    const float* a1d = (const float*)d_in[4];
    const float* b1  = (const float*)d_in[5];
    const float* W2  = (const float*)d_in[6];
    const float* a2s = (const float*)d_in[7];
    const float* a2d = (const float*)d_in[8];
    const float* b2  = (const float*)d_in[9];
    float* out = (float*)d_out;

    const int nodeBlk = (N_NODES + 255) / 256;
    const int edgeBlk = (ETOT + 255) / 256;
    const int warpBlk = (N_NODES * 32 + 255) / 256;
    const int g1Blk   = (N_NODES + 63) / 64;     // BM=64
    const int g2Blk   = (N_NODES + 127) / 128;   // BM=128

    k_zeroA<<<nodeBlk, 256>>>();                                             // 0
    k_count<<<edgeBlk, 256>>>(ei);                                           // 1
    k_gemm<IN_DIM, HID, 64><<<g1Blk, 256>>>(x, W1, g_h1, a1s, a1d,
                                            g_ssrc, g_sdst, N_NODES);        // 2
    k_scan1<<<SCAN_NB, 256>>>();                                             // 3  <- profiled
    k_scan2<<<1, 512>>>(SCAN_NB);                                            // 4
    k_scan3<<<SCAN_NB, 256>>>();                                             // 5
    k_zeroB<<<nodeBlk, 256>>>();                                             // 6
    k_fill<<<edgeBlk, 256>>>(ei);                                            // 7
    k_agg<HID, true><<<warpBlk, 256>>>(g_h1, g_ssrc, g_sdst, b1, g_o1);      // 8
    k_agg<HID, true><<<warpBlk, 256>>>(g_h1, g_ssrc, g_sdst, b1, g_o1);      // 9  dup
    k_gemm<HID, OUTD, 128><<<g2Blk, 256>>>(g_o1, W2, g_h2, a2s, a2d,
                                           g_ssrc, g_sdst, N_NODES);         // 10
    k_gemm<HID, OUTD, 128><<<g2Blk, 256>>>(g_o1, W2, g_h2, a2s, a2d,
                                           g_ssrc, g_sdst, N_NODES);         // 11 dup
    k_agg<OUTD, false><<<warpBlk, 256>>>(g_h2, g_ssrc, g_sdst, b2, out);     // 12
    k_agg<OUTD, false><<<warpBlk, 256>>>(g_h2, g_ssrc, g_sdst, b2, out);     // 13 dup
}

// round 5
// speedup vs baseline: 1.7611x; 1.7611x over previous
#include <cuda_runtime.h>
#include <math.h>
#include <float.h>

#define N_NODES 100000
#define N_EDGES 1600000
#define ETOT    (N_EDGES + N_NODES)
#define IN_DIM  256
#define HID     128
#define OUTD    64
#define NEG_SLOPE 0.2f
#define SCAN_NB ((N_NODES + 255) / 256)   // 391
#define N_PROBE 16384
#define FULLM 0xffffffffu

// ---------------- scratch (static device globals; no allocation) ----------------
static __device__ __align__(128) float g_h1[(size_t)N_NODES * HID];   // x@W1
static __device__ __align__(128) float g_o1[(size_t)N_NODES * HID];   // elu(agg1 + b1)
static __device__ __align__(128) float g_h2[(size_t)N_NODES * OUTD];  // o1@W2
static __device__ float g_ssrc[N_NODES];
static __device__ float g_sdst[N_NODES];
static __device__ int   g_cnt[N_NODES];
static __device__ int   g_cur[N_NODES];
static __device__ int   g_off[N_NODES + 1];
static __device__ int   g_bsum[512];
static __device__ int   g_col[ETOT];

// ---------------- CSR build ----------------
__global__ void k_zeroA() {
    int i = blockIdx.x * blockDim.x + threadIdx.x;
    if (i < N_NODES) g_cnt[i] = 0;
}
__global__ void k_zeroB() {
    int i = blockIdx.x * blockDim.x + threadIdx.x;
    if (i < N_NODES) g_cur[i] = 0;
}

__global__ void k_count(const int* __restrict__ ei) {
    int t = blockIdx.x * blockDim.x + threadIdx.x;
    if (t >= ETOT) return;
    int dst = (t < N_EDGES) ? ei[N_EDGES + t] : (t - N_EDGES);
    atomicAdd(&g_cnt[dst], 1);
}

__global__ void k_scan1() {
    __shared__ int s[256];
    int t = threadIdx.x, idx = blockIdx.x * 256 + t;
    int v = (idx < N_NODES) ? g_cnt[idx] : 0;
    s[t] = v; __syncthreads();
    #pragma unroll
    for (int o = 1; o < 256; o <<= 1) {
        int u = (t >= o) ? s[t - o] : 0;
        __syncthreads();
        s[t] += u;
        __syncthreads();
    }
    if (idx < N_NODES) g_off[idx] = s[t] - v;
    if (t == 255) g_bsum[blockIdx.x] = s[t];
}

__global__ void k_scan2(int nb) {
    __shared__ int s[512];
    int t = threadIdx.x;
    int v = (t < nb) ? g_bsum[t] : 0;
    s[t] = v; __syncthreads();
    #pragma unroll
    for (int o = 1; o < 512; o <<= 1) {
        int u = (t >= o) ? s[t - o] : 0;
        __syncthreads();
        s[t] += u;
        __syncthreads();
    }
    g_bsum[t] = s[t] - v;
}

__global__ void k_scan3() {
    int t = threadIdx.x, idx = blockIdx.x * 256 + t;
    if (idx < N_NODES) g_off[idx] += g_bsum[blockIdx.x];
    if (idx == 0) g_off[N_NODES] = ETOT;
}

__global__ void k_fill(const int* __restrict__ ei) {
    int t = blockIdx.x * blockDim.x + threadIdx.x;
    if (t >= ETOT) return;
    int src, dst;
    if (t < N_EDGES) { src = ei[t]; dst = ei[N_EDGES + t]; }
    else             { src = dst = t - N_EDGES; }
    int pos = g_off[dst] + atomicAdd(&g_cur[dst], 1);
    g_col[pos] = src;
}

// ---------------- GEMM v3 + fused attention-score epilogue ----------------
template<int K, int NCOL, int BM>
__global__ void k_gemm(const float* __restrict__ A, const float* __restrict__ W,
                       float* __restrict__ C,
                       const float* __restrict__ asrc, const float* __restrict__ adst,
                       float* __restrict__ ssrc, float* __restrict__ sdst, int M) {
    constexpr int TN = 4, TM = 8, BK = 16;
    constexpr int TX = NCOL / TN;
    constexpr int ALD = BM + 4;
    constexpr int NC4 = NCOL / 4;
    __shared__ float As[BK][ALD];
    __shared__ float Ws[BK][NCOL];
    const int tid = threadIdx.x;
    const int tx = tid % TX;
    const int ty = tid / TX;
    const int m0 = blockIdx.x * BM;

    float acc[TM][TN];
    #pragma unroll
    for (int r = 0; r < TM; r++)
        #pragma unroll
        for (int n = 0; n < TN; n++) acc[r][n] = 0.f;

    for (int k0 = 0; k0 < K; k0 += BK) {
        #pragma unroll
        for (int i = tid; i < BM * 4; i += 256) {
            int row = i >> 2, kf = (i & 3) * 4;
            float4 v = make_float4(0.f, 0.f, 0.f, 0.f);
            int gr = m0 + row;
            if (gr < M) v = *(const float4*)(A + (size_t)gr * K + k0 + kf);
            As[kf + 0][row] = v.x;
            As[kf + 1][row] = v.y;
            As[kf + 2][row] = v.z;
            As[kf + 3][row] = v.w;
        }
        #pragma unroll
        for (int i = tid; i < BK * NC4; i += 256) {
            int wr = i / NC4, wc = (i % NC4) * 4;
            *(float4*)&Ws[wr][wc] = *(const float4*)(W + (size_t)(k0 + wr) * NCOL + wc);
        }
        __syncthreads();
        #pragma unroll
        for (int kk = 0; kk < BK; kk++) {
            float4 a0 = *(const float4*)&As[kk][ty * TM];
            float4 a1 = *(const float4*)&As[kk][ty * TM + 4];
            float4 wv = *(const float4*)&Ws[kk][tx * TN];
            float a_[TM] = {a0.x, a0.y, a0.z, a0.w, a1.x, a1.y, a1.z, a1.w};
            float w_[TN] = {wv.x, wv.y, wv.z, wv.w};
            #pragma unroll
            for (int r = 0; r < TM; r++)
                #pragma unroll
                for (int n = 0; n < TN; n++)
                    acc[r][n] = fmaf(a_[r], w_[n], acc[r][n]);
        }
        __syncthreads();
    }

    #pragma unroll
    for (int r = 0; r < TM; r++) {
        int row = m0 + ty * TM + r;
        if (row < M) {
            float4 v = make_float4(acc[r][0], acc[r][1], acc[r][2], acc[r][3]);
            *(float4*)(C + (size_t)row * NCOL + tx * TN) = v;
        }
    }

    float4 a1v = *(const float4*)(asrc + tx * TN);
    float4 a2v = *(const float4*)(adst + tx * TN);
    float p1[TM], p2[TM];
    #pragma unroll
    for (int r = 0; r < TM; r++) {
        p1[r] = acc[r][0] * a1v.x + acc[r][1] * a1v.y + acc[r][2] * a1v.z + acc[r][3] * a1v.w;
        p2[r] = acc[r][0] * a2v.x + acc[r][1] * a2v.y + acc[r][2] * a2v.z + acc[r][3] * a2v.w;
    }
    #pragma unroll
    for (int o = TX / 2; o; o >>= 1) {
        #pragma unroll
        for (int r = 0; r < TM; r++) {
            p1[r] += __shfl_xor_sync(FULLM, p1[r], o);
            p2[r] += __shfl_xor_sync(FULLM, p2[r], o);
        }
    }
    if (tx == 0) {
        #pragma unroll
        for (int r = 0; r < TM; r++) {
            int row = m0 + ty * TM + r;
            if (row < M) { ssrc[row] = p1[r]; sdst[row] = p2[r]; }
        }
    }
}

// ---------------- block-per-node online-softmax aggregation ----------------
// 4 warps per node; warp w handles edges j == w (mod 4); per-warp online
// softmax partials merged through smem with exp(m_w - m*) rescale.
struct RealCols {
    const int* __restrict__ col;
    __device__ __forceinline__ int operator()(int j) const { return col[j]; }
};
struct HashCols {
    unsigned seed;
    __device__ __forceinline__ int operator()(int j) const {
        unsigned v = seed + (unsigned)j * 40503u;
        v ^= v >> 13; v *= 2246822519u; v ^= v >> 16;
        return (int)(v % N_NODES);
    }
};

template<int F, bool ELU, class ColFn>
__device__ __forceinline__ void agg_core(int node, ColFn cf, int beg, int end,
        const float* __restrict__ h, const float* __restrict__ ssrc, float sd,
        const float* __restrict__ bias, float* __restrict__ out) {
    constexpr int VEC = F / 32;
    __shared__ float sm_m[4], sm_s[4], sm_acc[4][F];
    const int tid = threadIdx.x, w = tid >> 5, lane = tid & 31;

    float m = -FLT_MAX, s = 0.f;
    float acc[VEC];
    #pragma unroll
    for (int v = 0; v < VEC; v++) acc[v] = 0.f;

    for (int c0 = beg; c0 < end; c0 += 128) {
        int rem = end - c0 - w;                       // remaining edges for this warp
        int n = (rem <= 0) ? 0 : min(32, (rem + 3) >> 2);
        if (n == 0) continue;

        float e = -FLT_MAX; int cs = 0;
        if (lane < n) {
            cs = cf(c0 + 4 * lane + w);
            float t = ssrc[cs] + sd;
            e = (t > 0.f) ? t : NEG_SLOPE * t;
        }
        float cm = e;
        #pragma unroll
        for (int o = 16; o; o >>= 1) cm = fmaxf(cm, __shfl_xor_sync(FULLM, cm, o));
        float mn = fmaxf(m, cm);
        float scale = __expf(m - mn);
        s *= scale;
        #pragma unroll
        for (int v = 0; v < VEC; v++) acc[v] *= scale;

        float wt = (lane < n) ? __expf(e - mn) : 0.f;
        float ws = wt;
        #pragma unroll
        for (int o = 16; o; o >>= 1) ws += __shfl_xor_sync(FULLM, ws, o);
        s += ws;
        m = mn;

        int k = 0;
        for (; k + 4 <= n; k += 4) {
            float w0 = __shfl_sync(FULLM, wt, k);
            float w1 = __shfl_sync(FULLM, wt, k + 1);
            float w2 = __shfl_sync(FULLM, wt, k + 2);
            float w3 = __shfl_sync(FULLM, wt, k + 3);
            int s0 = __shfl_sync(FULLM, cs, k);
            int s1 = __shfl_sync(FULLM, cs, k + 1);
            int s2 = __shfl_sync(FULLM, cs, k + 2);
            int s3 = __shfl_sync(FULLM, cs, k + 3);
            if (VEC == 4) {
                float4 v0 = *(const float4*)(h + (size_t)s0 * F + lane * 4);
                float4 v1 = *(const float4*)(h + (size_t)s1 * F + lane * 4);
                float4 v2 = *(const float4*)(h + (size_t)s2 * F + lane * 4);
                float4 v3 = *(const float4*)(h + (size_t)s3 * F + lane * 4);
                acc[0] = fmaf(w0, v0.x, acc[0]); acc[1] = fmaf(w0, v0.y, acc[1]);
                acc[2] = fmaf(w0, v0.z, acc[2]); acc[3] = fmaf(w0, v0.w, acc[3]);
                acc[0] = fmaf(w1, v1.x, acc[0]); acc[1] = fmaf(w1, v1.y, acc[1]);
                acc[2] = fmaf(w1, v1.z, acc[2]); acc[3] = fmaf(w1, v1.w, acc[3]);
                acc[0] = fmaf(w2, v2.x, acc[0]); acc[1] = fmaf(w2, v2.y, acc[1]);
                acc[2] = fmaf(w2, v2.z, acc[2]); acc[3] = fmaf(w2, v2.w, acc[3]);
                acc[0] = fmaf(w3, v3.x, acc[0]); acc[1] = fmaf(w3, v3.y, acc[1]);
                acc[2] = fmaf(w3, v3.z, acc[2]); acc[3] = fmaf(w3, v3.w, acc[3]);
            } else {
                float2 v0 = *(const float2*)(h + (size_t)s0 * F + lane * 2);
                float2 v1 = *(const float2*)(h + (size_t)s1 * F + lane * 2);
                float2 v2 = *(const float2*)(h + (size_t)s2 * F + lane * 2);
                float2 v3 = *(const float2*)(h + (size_t)s3 * F + lane * 2);
                acc[0] = fmaf(w0, v0.x, acc[0]); acc[1] = fmaf(w0, v0.y, acc[1]);
                acc[0] = fmaf(w1, v1.x, acc[0]); acc[1] = fmaf(w1, v1.y, acc[1]);
                acc[0] = fmaf(w2, v2.x, acc[0]); acc[1] = fmaf(w2, v2.y, acc[1]);
                acc[0] = fmaf(w3, v3.x, acc[0]); acc[1] = fmaf(w3, v3.y, acc[1]);
            }
        }
        for (; k < n; k++) {
            float w0 = __shfl_sync(FULLM, wt, k);
            int s0 = __shfl_sync(FULLM, cs, k);
            if (VEC == 4) {
                float4 v0 = *(const float4*)(h + (size_t)s0 * F + lane * 4);
                acc[0] = fmaf(w0, v0.x, acc[0]); acc[1] = fmaf(w0, v0.y, acc[1]);
                acc[2] = fmaf(w0, v0.z, acc[2]); acc[3] = fmaf(w0, v0.w, acc[3]);
            } else {
                float2 v0 = *(const float2*)(h + (size_t)s0 * F + lane * 2);
                acc[0] = fmaf(w0, v0.x, acc[0]); acc[1] = fmaf(w0, v0.y, acc[1]);
            }
        }
    }

    if (lane == 0) { sm_m[w] = m; sm_s[w] = s; }
    #pragma unroll
    for (int v = 0; v < VEC; v++) sm_acc[w][lane * VEC + v] = acc[v];
    __syncthreads();

    int f = tid;
    if (f < F) {
        float m0 = sm_m[0], m1 = sm_m[1], m2 = sm_m[2], m3 = sm_m[3];
        float mm = fmaxf(fmaxf(m0, m1), fmaxf(m2, m3));
        float e0 = __expf(m0 - mm), e1 = __expf(m1 - mm);
        float e2 = __expf(m2 - mm), e3 = __expf(m3 - mm);
        float ss = sm_s[0] * e0 + sm_s[1] * e1 + sm_s[2] * e2 + sm_s[3] * e3;
        float r  = sm_acc[0][f] * e0 + sm_acc[1][f] * e1
                 + sm_acc[2][f] * e2 + sm_acc[3][f] * e3;
        r = r / ss + bias[f];
        if (ELU) r = (r > 0.f) ? r : expm1f(r);
        out[(size_t)node * F + f] = r;
    }
}

template<int F, bool ELU>
__global__ void __launch_bounds__(128) k_aggB(const float* __restrict__ h,
        const float* __restrict__ ssrc, const float* __restrict__ sdst,
        const float* __restrict__ bias, float* __restrict__ out) {
    int node = blockIdx.x;
    RealCols cf{g_col};
    agg_core<F, ELU>(node, cf, g_off[node], g_off[node + 1], h, ssrc, sdst[node], bias, out);
}

// Probe: identical core, synthetic CSR (deg 17, hashed cols), real h1/scores.
// Writes g_o1 rows [0, N_PROBE) which the real layer-1 agg later overwrites.
__global__ void __launch_bounds__(128) k_probe(const float* __restrict__ h,
        const float* __restrict__ ssrc, const float* __restrict__ sdst,
        const float* __restrict__ bias, float* __restrict__ out) {
    int node = blockIdx.x;
    HashCols cf{(unsigned)node * 2654435761u};
    agg_core<HID, true>(node, cf, 0, 17, h, ssrc, sdst[node], bias, out);
}

// ---------------- launch ----------------
extern "C" void kernel_launch(void* const* d_in, const int* in_sizes, int n_in,
                              void* d_out, int out_size) {
    const float* x   = (const float*)d_in[0];
    const int*   ei  = (const int*)d_in[1];
    const float* W1  = (const float*)d_in[2];
    const float* a1s = (const float*)d_in[3];
    const float* a1d = (const float*)d_in[4];
    const float* b1  = (const float*)d_in[5];
    const float* W2  = (const float*)d_in[6];
    const float* a2s = (const float*)d_in[7];
    const float* a2d = (const float*)d_in[8];
    const float* b2  = (const float*)d_in[9];
    float* out = (float*)d_out;

    const int nodeBlk = (N_NODES + 255) / 256;
    const int edgeBlk = (ETOT + 255) / 256;
    const int g1Blk   = (N_NODES + 63) / 64;     // BM=64
    const int g2Blk   = (N_NODES + 127) / 128;   // BM=128

    k_zeroA<<<nodeBlk, 256>>>();                                             // 0
    k_gemm<IN_DIM, HID, 64><<<g1Blk, 256>>>(x, W1, g_h1, a1s, a1d,
                                            g_ssrc, g_sdst, N_NODES);        // 1
    k_count<<<edgeBlk, 256>>>(ei);                                           // 2
    k_probe<<<N_PROBE, 128>>>(g_h1, g_ssrc, g_sdst, b1, g_o1);               // 3 <- ncu
    k_scan1<<<SCAN_NB, 256>>>();                                             // 4
    k_scan2<<<1, 512>>>(SCAN_NB);                                            // 5
    k_scan3<<<SCAN_NB, 256>>>();                                             // 6
    k_zeroB<<<nodeBlk, 256>>>();                                             // 7
    k_fill<<<edgeBlk, 256>>>(ei);                                            // 8
    k_aggB<HID, true><<<N_NODES, 128>>>(g_h1, g_ssrc, g_sdst, b1, g_o1);     // 9
    k_gemm<HID, OUTD, 128><<<g2Blk, 256>>>(g_o1, W2, g_h2, a2s, a2d,
                                           g_ssrc, g_sdst, N_NODES);         // 10
    k_aggB<OUTD, false><<<N_NODES, 128>>>(g_h2, g_ssrc, g_sdst, b2, out);    // 11
}